// round 5
// baseline (speedup 1.0000x reference)
#include <cuda_runtime.h>
#include <cuda_fp16.h>
#include <cstdint>

// ---------------- problem constants ----------------
#define BTOT 7200      // bs*nq
#define N1   32768     // 2*E*D
#define N2   16384     // E*D
#define NS1  4         // k1 N-split

// ---------------- smem layout (bytes from dynamic base) ----------------
#define A_STRIDE 528               // 64 rows x 528B (256 fp16 + 16B pad)
#define B_OFF    33792             // A ends here
#define B_STRIDE 144               // 64 fp16 (128B) + 16B pad -> LDSM conflict-free
#define B_STAGE  18432             // 128 rows x 144B
#define B_END    (B_OFF + 3*B_STAGE)   // 89088
#define SMEM_1   B_END                         // k1: f1a overlays B region
#define SMEM_2   (B_END + 64*33*4)             // 97536: f1s after B
#define SMEM_3K  (B_END + 64*260*4)            // 155648: f3a after B

// ---------------- device scratch (allocation-free rule) ----------------
__device__ __half g_qh   [BTOT * 256];
__device__ __half g_wpreh[(size_t)N1 * 256];
__device__ __half g_wafth[(size_t)N2 * 256];
__device__ __half g_wouth[256 * 256];
__device__ float  g_f1p  [NS1 * BTOT * 64];   // k1 partials
__device__ float  g_f1n  [BTOT * 64];         // LN1 output
__device__ float  g_f2p  [2 * BTOT * 256];    // k2 partials per d-split
__device__ __half g_f2nh [BTOT * 256];        // LN2 output (fp16)

// ---------------- PTX helpers ----------------
__device__ __forceinline__ void mma_f16(float* c, const uint32_t* a, uint32_t b0, uint32_t b1) {
    asm volatile(
        "mma.sync.aligned.m16n8k16.row.col.f32.f16.f16.f32 "
        "{%0,%1,%2,%3}, {%4,%5,%6,%7}, {%8,%9}, {%0,%1,%2,%3};"
        : "+f"(c[0]), "+f"(c[1]), "+f"(c[2]), "+f"(c[3])
        : "r"(a[0]), "r"(a[1]), "r"(a[2]), "r"(a[3]), "r"(b0), "r"(b1));
}

__device__ __forceinline__ void ldsm4(uint32_t& r0, uint32_t& r1, uint32_t& r2, uint32_t& r3,
                                      uint32_t addr) {
    asm volatile("ldmatrix.sync.aligned.m8n8.x4.shared.b16 {%0,%1,%2,%3}, [%4];"
        : "=r"(r0), "=r"(r1), "=r"(r2), "=r"(r3) : "r"(addr));
}

__device__ __forceinline__ void cp16z(uint32_t s, const void* g, uint32_t sz) {
    asm volatile("cp.async.cg.shared.global [%0], [%1], 16, %2;" :: "r"(s), "l"(g), "r"(sz));
}
__device__ __forceinline__ void cp16(uint32_t s, const void* g) {
    asm volatile("cp.async.cg.shared.global [%0], [%1], 16;" :: "r"(s), "l"(g));
}
#define CP_COMMIT asm volatile("cp.async.commit_group;" ::: "memory")
#define CP_WAIT0  asm volatile("cp.async.wait_group 0;" ::: "memory")
#define CP_WAIT1  asm volatile("cp.async.wait_group 1;" ::: "memory")
#define CP_WAIT2  asm volatile("cp.async.wait_group 2;" ::: "memory")

// ---------------- A tile load: 64 rows x 256 fp16 (one commit group) --------
__device__ __forceinline__ void load_A(uint32_t A, const __half* __restrict__ src,
                                       int m0, int tid) {
#pragma unroll
    for (int it = 0; it < 8; it++) {
        int idx = tid + it * 256;           // 0..2047
        int r = idx >> 5, c16 = idx & 31;
        uint32_t dst = A + r * A_STRIDE + c16 * 16;
        int gr = m0 + r;
        bool v = gr < BTOT;
        const __half* g = src + (v ? ((size_t)gr * 256 + c16 * 8) : 0);
        cp16z(dst, g, v ? 16u : 0u);
    }
    CP_COMMIT;
}

// ---------------- B chunk: 128 N-rows x 64 K-cols (one commit group) --------
__device__ __forceinline__ void issue_B(uint32_t Bst, const __half* __restrict__ W,
                                        int p0, int ch, int tid) {
#pragma unroll
    for (int it = 0; it < 4; it++) {
        int idx = tid + it * 256;           // 0..1023
        int row = idx >> 3, c16 = idx & 7;
        cp16(Bst + row * B_STRIDE + c16 * 16,
             W + (size_t)(p0 + row) * 256 + ch * 64 + c16 * 8);
    }
    CP_COMMIT;
}

__device__ __forceinline__ void frag_addrs(uint32_t A, int wm, int wn, int lane,
                                           uint32_t& aaddr0, uint32_t& aaddr1, uint32_t& boff) {
    int a_row = ((lane >> 3) & 1) * 8 + (lane & 7);
    int a_cj  = lane >> 4;
    aaddr0 = A + (uint32_t)(wm * 32 + a_row) * A_STRIDE + (uint32_t)a_cj * 16;
    aaddr1 = aaddr0 + 16 * A_STRIDE;
    int b_row = (lane >> 4) * 8 + (lane & 7);
    int b_cj  = (lane >> 3) & 1;
    boff = (uint32_t)(wn * 32 + b_row) * B_STRIDE + (uint32_t)b_cj * 16;
}

// One 64-K chunk of MMAs: 16 LDSM + 32 HMMA per warp.
__device__ __forceinline__ void chunk_mma(uint32_t aaddr0, uint32_t aaddr1, uint32_t Bst,
                                          uint32_t boff, uint32_t kb, float cacc[2][4][4]) {
#pragma unroll
    for (int ks = 0; ks < 4; ks++) {
        const uint32_t ka = kb + (uint32_t)ks * 32;
        uint32_t a[2][4];
        ldsm4(a[0][0], a[0][1], a[0][2], a[0][3], aaddr0 + ka);
        ldsm4(a[1][0], a[1][1], a[1][2], a[1][3], aaddr1 + ka);
        uint32_t b[4][2];
        ldsm4(b[0][0], b[0][1], b[1][0], b[1][1], Bst + boff + ks * 32);
        ldsm4(b[2][0], b[2][1], b[3][0], b[3][1], Bst + boff + ks * 32 + 16 * B_STRIDE);
#pragma unroll
        for (int nf = 0; nf < 4; nf++) {
            mma_f16(cacc[0][nf], a[0], b[nf][0], b[nf][1]);
            mma_f16(cacc[1][nf], a[1], b[nf][0], b[nf][1]);
        }
    }
}

#define ZERO_ACC(cacc) do { \
    _Pragma("unroll") for (int mi = 0; mi < 2; mi++) \
    _Pragma("unroll") for (int ni = 0; ni < 4; ni++) \
    _Pragma("unroll") for (int e = 0; e < 4; e++) cacc[mi][ni][e] = 0.f; } while (0)

// ---------------- preround: fp32 -> fp16 ----------------
__global__ void __launch_bounds__(256, 8) preround_kernel(
    const float* __restrict__ q, const float* __restrict__ wpre,
    const float* __restrict__ waft, const float* __restrict__ wout)
{
    size_t i = (size_t)blockIdx.x * 256 + threadIdx.x;
    const size_t S1 = (size_t)N1 * 64;
    const size_t S2 = S1 + (size_t)N2 * 64;
    const size_t S3 = S2 + 256 * 64;
    const size_t S4 = S3 + (size_t)BTOT * 64;
    if (i >= S4) return;
    const float* src; __half* dst; size_t off;
    if (i < S1)      { src = wpre; dst = g_wpreh; off = i; }
    else if (i < S2) { src = waft; dst = g_wafth; off = i - S1; }
    else if (i < S3) { src = wout; dst = g_wouth; off = i - S2; }
    else             { src = q;    dst = g_qh;    off = i - S3; }
    float4 v = ((const float4*)src)[off];
    ((__half2*)dst)[off * 2]     = __floats2half2_rn(v.x, v.y);
    ((__half2*)dst)[off * 2 + 1] = __floats2half2_rn(v.z, v.w);
}

// ---------------- Stage 1: 64 tiles, continuous 256-chunk stream ----------------
__global__ void __launch_bounds__(256, 2) k1_kernel(
    const float* __restrict__ feats, const float* __restrict__ bpre)
{
    extern __shared__ unsigned char sm[];
    uint32_t sb = (uint32_t)__cvta_generic_to_shared(sm);
    const uint32_t A = sb, B = sb + B_OFF;
    float* f1a = (float*)(sm + B_OFF);    // overlays B region (used after mainloop)

    const int tid = threadIdx.x, warp = tid >> 5, lane = tid & 31;
    const int wm = warp >> 2, wn = warp & 3;
    const int gID = lane >> 2, t4 = lane & 3;
    const int m0 = blockIdx.x * 64;
    const int nt0 = blockIdx.y * 64;
    const int h = wn >> 1;

    uint32_t aaddr0, aaddr1, boff;
    frag_addrs(A, wm, wn, lane, aaddr0, aaddr1, boff);

    load_A(A, g_qh, m0, tid);
    issue_B(B,           g_wpreh, nt0 << 7, 0, tid);
    issue_B(B + B_STAGE, g_wpreh, nt0 << 7, 1, tid);
    CP_WAIT2;              // A tile resident
    __syncthreads();

    float freg[2][4][4];
    ZERO_ACC(freg);
    float cacc[2][4][4];
    ZERO_ACC(cacc);

    const int G = 256;     // 64 tiles x 4 chunks
    for (int g = 0; g < G; g++) {
        if (g < G - 1) CP_WAIT1; else CP_WAIT0;
        __syncthreads();
        if (g + 2 < G) {
            int gn = g + 2;
            issue_B(B + (gn % 3) * B_STAGE, g_wpreh, (nt0 + (gn >> 2)) << 7, gn & 3, tid);
        }
        chunk_mma(aaddr0, aaddr1, B + (g % 3) * B_STAGE, boff, (uint32_t)(g & 3) * 128, cacc);

        if ((g & 3) == 3) {
            const int t = g >> 2;
            const int p0 = (nt0 + t) << 7;
            const int kf = p0 >> 6;
            float fv[2][2];
#pragma unroll
            for (int mi = 0; mi < 2; mi++)
#pragma unroll
                for (int eh = 0; eh < 2; eh++) {
                    int b = m0 + wm * 32 + mi * 16 + gID + (eh << 3);
                    fv[mi][eh] = (b < BTOT) ? __ldg(&feats[(size_t)b * 512 + kf + h]) : 0.f;
                }
#pragma unroll
            for (int ni = 0; ni < 4; ni++) {
                int colb = wn * 32 + ni * 8 + t4 * 2;
                float b0 = __ldg(&bpre[p0 + colb]);
                float b1 = __ldg(&bpre[p0 + colb + 1]);
#pragma unroll
                for (int mi = 0; mi < 2; mi++)
#pragma unroll
                    for (int e = 0; e < 4; e++) {
                        float bias = (e & 1) ? b1 : b0;
                        freg[mi][ni][e] += fv[mi][e >> 1] * (cacc[mi][ni][e] + bias);
                    }
            }
            ZERO_ACC(cacc);
        }
    }

    // reduce freg across warps via overlaid smem buffer
    __syncthreads();
    for (int i = tid; i < 64 * 65; i += 256) f1a[i] = 0.f;
    __syncthreads();
#pragma unroll
    for (int mi = 0; mi < 2; mi++)
#pragma unroll
        for (int ni = 0; ni < 4; ni++)
#pragma unroll
            for (int e = 0; e < 4; e++) {
                int row = wm * 32 + mi * 16 + gID + ((e >> 1) << 3);
                int col = wn * 32 + ni * 8 + t4 * 2 + (e & 1);
                atomicAdd(&f1a[row * 65 + (col & 63)], freg[mi][ni][e]);
            }
    __syncthreads();

    float* dst = g_f1p + (size_t)blockIdx.y * (BTOT * 64);
    for (int i = tid; i < 64 * 64; i += 256) {
        int r = i >> 6, d = i & 63;
        int b = m0 + r;
        if (b < BTOT) dst[(size_t)b * 64 + d] = f1a[r * 65 + d];
    }
}

// ---------------- LN1 ----------------
__global__ void __launch_bounds__(256, 8) ln1_kernel(
    const float* __restrict__ g1, const float* __restrict__ be1)
{
    int w = threadIdx.x >> 5, lane = threadIdx.x & 31;
    int b = blockIdx.x * 8 + w;
    if (b >= BTOT) return;
    int d = lane * 2;
    float v0 = 0.f, v1 = 0.f;
#pragma unroll
    for (int s = 0; s < NS1; s++) {
        float2 t = *(const float2*)(g_f1p + (size_t)s * (BTOT * 64) + (size_t)b * 64 + d);
        v0 += t.x; v1 += t.y;
    }
    float s1 = v0 + v1, s2 = v0 * v0 + v1 * v1;
#pragma unroll
    for (int o = 16; o; o >>= 1) {
        s1 += __shfl_xor_sync(0xffffffffu, s1, o);
        s2 += __shfl_xor_sync(0xffffffffu, s2, o);
    }
    float mu = s1 * (1.f / 64.f);
    float inv = rsqrtf(s2 * (1.f / 64.f) - mu * mu + 1e-5f);
    float y0 = fmaxf((v0 - mu) * inv * g1[d] + be1[d], 0.f);
    float y1 = fmaxf((v1 - mu) * inv * g1[d + 1] + be1[d + 1], 0.f);
    *(float2*)(g_f1n + (size_t)b * 64 + d) = make_float2(y0, y1);
}

// ---------------- Stage 2: 32 tiles, continuous 128-chunk stream ----------------
__global__ void __launch_bounds__(256, 2) k2_kernel(const float* __restrict__ baft)
{
    extern __shared__ unsigned char sm[];
    uint32_t sb = (uint32_t)__cvta_generic_to_shared(sm);
    const uint32_t A = sb, B = sb + B_OFF;
    float* f1s = (float*)(sm + B_END);    // 64 x 33 (only this block's d-range)

    const int tid = threadIdx.x, warp = tid >> 5, lane = tid & 31;
    const int wm = warp >> 2, wn = warp & 3;
    const int gID = lane >> 2, t4 = lane & 3;
    const int m0 = blockIdx.x * 64;
    const int e0 = blockIdx.y << 7;
    const int d0 = blockIdx.z << 5;

    uint32_t aaddr0, aaddr1, boff;
    frag_addrs(A, wm, wn, lane, aaddr0, aaddr1, boff);

    load_A(A, g_qh, m0, tid);
    issue_B(B,           g_wafth, (d0 << 8) + e0, 0, tid);
    issue_B(B + B_STAGE, g_wafth, (d0 << 8) + e0, 1, tid);

    for (int i = tid; i < 64 * 32; i += 256) {
        int r = i >> 5, j = i & 31;
        int b = m0 + r;
        f1s[r * 33 + j] = (b < BTOT) ? g_f1n[(size_t)b * 64 + d0 + j] : 0.f;
    }
    CP_WAIT2;
    __syncthreads();

    float facc[2][4][4];
    ZERO_ACC(facc);
    float cacc[2][4][4];
    ZERO_ACC(cacc);

    const int G = 128;     // 32 tiles x 4 chunks
    for (int g = 0; g < G; g++) {
        if (g < G - 1) CP_WAIT1; else CP_WAIT0;
        __syncthreads();
        if (g + 2 < G) {
            int gn = g + 2;
            issue_B(B + (gn % 3) * B_STAGE, g_wafth, ((d0 + (gn >> 2)) << 8) + e0, gn & 3, tid);
        }
        chunk_mma(aaddr0, aaddr1, B + (g % 3) * B_STAGE, boff, (uint32_t)(g & 3) * 128, cacc);

        if ((g & 3) == 3) {
            const int t = g >> 2;
            const int p0 = ((d0 + t) << 8) + e0;
            float fv[2][2];
#pragma unroll
            for (int mi = 0; mi < 2; mi++)
#pragma unroll
                for (int eh = 0; eh < 2; eh++) {
                    int r = wm * 32 + mi * 16 + gID + (eh << 3);
                    fv[mi][eh] = f1s[r * 33 + t];
                }
#pragma unroll
            for (int ni = 0; ni < 4; ni++) {
                int colb = wn * 32 + ni * 8 + t4 * 2;
                float b0 = __ldg(&baft[p0 + colb]);
                float b1 = __ldg(&baft[p0 + colb + 1]);
#pragma unroll
                for (int mi = 0; mi < 2; mi++)
#pragma unroll
                    for (int e = 0; e < 4; e++) {
                        float bias = (e & 1) ? b1 : b0;
                        facc[mi][ni][e] += fv[mi][e >> 1] * (cacc[mi][ni][e] + bias);
                    }
            }
            ZERO_ACC(cacc);
        }
    }

    float* dst = g_f2p + (size_t)blockIdx.z * (BTOT * 256);
#pragma unroll
    for (int mi = 0; mi < 2; mi++)
#pragma unroll
        for (int ni = 0; ni < 4; ni++)
#pragma unroll
            for (int e = 0; e < 4; e++) {
                int row = wm * 32 + mi * 16 + gID + ((e >> 1) << 3);
                int col = wn * 32 + ni * 8 + t4 * 2 + (e & 1);
                int b = m0 + row;
                if (b < BTOT) dst[(size_t)b * 256 + e0 + col] = facc[mi][ni][e];
            }
}

// ---------------- LN2 -> fp16 ----------------
__global__ void __launch_bounds__(256, 8) ln2_kernel(
    const float* __restrict__ g2, const float* __restrict__ be2)
{
    int w = threadIdx.x >> 5, lane = threadIdx.x & 31;
    int b = blockIdx.x * 8 + w;
    if (b >= BTOT) return;
    float v[8], s1 = 0.f, s2 = 0.f;
#pragma unroll
    for (int i = 0; i < 8; i++) {
        float x = g_f2p[(size_t)b * 256 + i * 32 + lane]
                + g_f2p[(size_t)BTOT * 256 + (size_t)b * 256 + i * 32 + lane];
        v[i] = x; s1 += x; s2 += x * x;
    }
#pragma unroll
    for (int o = 16; o; o >>= 1) {
        s1 += __shfl_xor_sync(0xffffffffu, s1, o);
        s2 += __shfl_xor_sync(0xffffffffu, s2, o);
    }
    float mu = s1 * (1.f / 256.f);
    float inv = rsqrtf(s2 * (1.f / 256.f) - mu * mu + 1e-5f);
#pragma unroll
    for (int i = 0; i < 8; i++) {
        int e = i * 32 + lane;
        float y = fmaxf((v[i] - mu) * inv * g2[e] + be2[e], 0.f);
        g_f2nh[(size_t)b * 256 + e] = __float2half_rn(y);
    }
}

// ---------------- Stage 3 + LN3 ----------------
__global__ void __launch_bounds__(256, 1) k3_kernel(
    const float* __restrict__ bout,
    const float* __restrict__ g3, const float* __restrict__ be3,
    float* __restrict__ out)
{
    extern __shared__ unsigned char sm[];
    uint32_t sb = (uint32_t)__cvta_generic_to_shared(sm);
    const uint32_t A = sb, B = sb + B_OFF;
    float* f3a = (float*)(sm + B_END);    // 64 x 260

    const int tid = threadIdx.x, warp = tid >> 5, lane = tid & 31;
    const int wm = warp >> 2, wn = warp & 3;
    const int gID = lane >> 2, t4 = lane & 3;
    const int m0 = blockIdx.x * 64;

    uint32_t aaddr0, aaddr1, boff;
    frag_addrs(A, wm, wn, lane, aaddr0, aaddr1, boff);

    load_A(A, g_f2nh, m0, tid);
    issue_B(B,           g_wouth, 0, 0, tid);
    issue_B(B + B_STAGE, g_wouth, 0, 1, tid);
    CP_WAIT2;
    __syncthreads();

    float cacc[2][4][4];
    ZERO_ACC(cacc);

    const int G = 8;       // 2 tiles x 4 chunks
    for (int g = 0; g < G; g++) {
        if (g < G - 1) CP_WAIT1; else CP_WAIT0;
        __syncthreads();
        if (g + 2 < G) {
            int gn = g + 2;
            issue_B(B + (gn % 3) * B_STAGE, g_wouth, (gn >> 2) << 7, gn & 3, tid);
        }
        chunk_mma(aaddr0, aaddr1, B + (g % 3) * B_STAGE, boff, (uint32_t)(g & 3) * 128, cacc);

        if ((g & 3) == 3) {
            const int p0 = (g >> 2) << 7;
#pragma unroll
            for (int mi = 0; mi < 2; mi++)
#pragma unroll
                for (int ni = 0; ni < 4; ni++)
#pragma unroll
                    for (int e = 0; e < 4; e++) {
                        int row = wm * 32 + mi * 16 + gID + ((e >> 1) << 3);
                        int col = wn * 32 + ni * 8 + t4 * 2 + (e & 1);
                        f3a[row * 260 + p0 + col] = cacc[mi][ni][e] + __ldg(&bout[p0 + col]);
                    }
            ZERO_ACC(cacc);
        }
    }
    __syncthreads();

    const int row = tid >> 2;
    const int b = m0 + row;
    if (b < BTOT) {
        const int e0 = (tid & 3) * 64;
        float s1 = 0.f, s2 = 0.f;
#pragma unroll
        for (int i = 0; i < 64; i++) {
            float x = f3a[row * 260 + e0 + i];
            s1 += x; s2 += x * x;
        }
        s1 += __shfl_xor_sync(0xffffffffu, s1, 1); s1 += __shfl_xor_sync(0xffffffffu, s1, 2);
        s2 += __shfl_xor_sync(0xffffffffu, s2, 1); s2 += __shfl_xor_sync(0xffffffffu, s2, 2);
        float mu = s1 * (1.f / 256.f);
        float inv = rsqrtf(s2 * (1.f / 256.f) - mu * mu + 1e-5f);
#pragma unroll
        for (int i = 0; i < 64; i++) {
            int e = e0 + i;
            float y = (f3a[row * 260 + e] - mu) * inv * g3[e] + be3[e];
            out[(size_t)b * 256 + e] = fmaxf(y, 0.f);
        }
    }
}

// ---------------- host launch ----------------
extern "C" void kernel_launch(void* const* d_in, const int* in_sizes, int n_in,
                              void* d_out, int out_size)
{
    const float* q     = (const float*)d_in[0];
    const float* feats = (const float*)d_in[1];
    const float* Wpre  = (const float*)d_in[2];
    const float* bpre  = (const float*)d_in[3];
    const float* Waft  = (const float*)d_in[4];
    const float* baft  = (const float*)d_in[5];
    const float* Wout  = (const float*)d_in[6];
    const float* bout  = (const float*)d_in[7];
    const float* g1  = (const float*)d_in[8];
    const float* be1 = (const float*)d_in[9];
    const float* g2  = (const float*)d_in[10];
    const float* be2 = (const float*)d_in[11];
    const float* g3  = (const float*)d_in[12];
    const float* be3 = (const float*)d_in[13];
    float* out = (float*)d_out;

    cudaFuncSetAttribute(k1_kernel, cudaFuncAttributeMaxDynamicSharedMemorySize, SMEM_1);
    cudaFuncSetAttribute(k2_kernel, cudaFuncAttributeMaxDynamicSharedMemorySize, SMEM_2);
    cudaFuncSetAttribute(k3_kernel, cudaFuncAttributeMaxDynamicSharedMemorySize, SMEM_3K);

    const size_t nf4 = (size_t)N1 * 64 + (size_t)N2 * 64 + 256 * 64 + (size_t)BTOT * 64;
    int pr_blocks = (int)((nf4 + 255) / 256);

    dim3 blk(256);
    preround_kernel<<<pr_blocks, blk>>>(q, Wpre, Waft, Wout);
    k1_kernel<<<dim3(113, NS1), blk, SMEM_1>>>(feats, bpre);
    ln1_kernel<<<dim3(900), blk>>>(g1, be1);
    k2_kernel<<<dim3(113, 2, 2), blk, SMEM_2>>>(baft);
    ln2_kernel<<<dim3(900), blk>>>(g2, be2);
    k3_kernel<<<dim3(113), blk, SMEM_3K>>>(bout, g3, be3, out);
}